// round 3
// baseline (speedup 1.0000x reference)
#include <cuda_runtime.h>

#define Bb 8
#define Nn 4096
#define Ff 240
#define Hh 32
#define Ll 240
#define NC (Bb * Hh)   // 256 folded columns

// Scratch (allocation-free rule: __device__ globals)
__device__ float g_H[Nn * NC];   // H2[m][b*32+h], 4 MB
__device__ float g_R[Nn * NC];   // relu(a@H2 + b1), 4 MB

// ---------------------------------------------------------------------------
// K1: H2[m, b*32+h] = sum_f x[b,m,f] * W1[f,h]
// block (8,32): tx = h-group (4 h each), ty = row. grid (N/32, B).
// W1 staged in smem; x rows streamed as float4 from gmem (L1-friendly).
// ---------------------------------------------------------------------------
__global__ __launch_bounds__(256) void k1_xw1(const float* __restrict__ x,
                                              const float* __restrict__ W1) {
    __shared__ float W1s[Ff][Hh];              // 30 KB
    int tid = threadIdx.y * 8 + threadIdx.x;
    for (int i = tid; i < Ff * Hh; i += 256)
        W1s[i / Hh][i % Hh] = W1[i];
    __syncthreads();

    int b   = blockIdx.y;
    int row = blockIdx.x * 32 + threadIdx.y;
    const float* xr = x + ((size_t)b * Nn + row) * Ff;
    int h0 = threadIdx.x * 4;

    float acc0 = 0.f, acc1 = 0.f, acc2 = 0.f, acc3 = 0.f;
    #pragma unroll 4
    for (int f4 = 0; f4 < Ff / 4; f4++) {
        float4 xv = reinterpret_cast<const float4*>(xr)[f4];
        int f = f4 * 4;
        float4 wa = *reinterpret_cast<const float4*>(&W1s[f + 0][h0]);
        float4 wb = *reinterpret_cast<const float4*>(&W1s[f + 1][h0]);
        float4 wc = *reinterpret_cast<const float4*>(&W1s[f + 2][h0]);
        float4 wd = *reinterpret_cast<const float4*>(&W1s[f + 3][h0]);
        acc0 += xv.x * wa.x + xv.y * wb.x + xv.z * wc.x + xv.w * wd.x;
        acc1 += xv.x * wa.y + xv.y * wb.y + xv.z * wc.y + xv.w * wd.y;
        acc2 += xv.x * wa.z + xv.y * wb.z + xv.z * wc.z + xv.w * wd.z;
        acc3 += xv.x * wa.w + xv.y * wb.w + xv.z * wc.w + xv.w * wd.w;
    }
    float* dst = &g_H[(size_t)row * NC + b * Hh + h0];
    dst[0] = acc0; dst[1] = acc1; dst[2] = acc2; dst[3] = acc3;
}

// ---------------------------------------------------------------------------
// K2: R[m,c] = relu( sum_k a[m,k] * H2[k,c] + b1[c % 32] )
// GEMM M=4096, N=256, K=4096. BM=32, BN=64, BK=32; 256 thr; 2x4 per thread.
// grid (128, 4) = 512 blocks — ~3.5 waves on 148 SMs.
// ---------------------------------------------------------------------------
#define BM 32
#define BN 64
#define BK 32

__global__ __launch_bounds__(256) void k2_agg(const float* __restrict__ a,
                                              const float* __restrict__ b1) {
    __shared__ float As[BK][BM + 1];   // stored k-major (transposed), padded
    __shared__ float Bs[BK][BN];

    int tid = threadIdx.x;
    int bm = blockIdx.x, bn = blockIdx.y;

    int tx = tid % 16;       // col group: 4 cols
    int ty = tid / 16;       // row group: 2 rows

    // a-tile load mapping: one float4 per thread
    int ar = tid / 8;              // 0..31 (row within tile)
    int ak = (tid % 8) * 4;        // k offset (float4)

    const float* a_row = a + ((size_t)(bm * BM + ar)) * Nn + ak;

    float acc[2][4] = {};

    for (int k0 = 0; k0 < Nn; k0 += BK) {
        // load A tile (32x32 floats), scatter to k-major smem
        float4 av = *reinterpret_cast<const float4*>(a_row + k0);
        As[ak + 0][ar] = av.x;
        As[ak + 1][ar] = av.y;
        As[ak + 2][ar] = av.z;
        As[ak + 3][ar] = av.w;
        // load B tile (32x64 floats) = 2 float4 per thread
        #pragma unroll
        for (int i = 0; i < 2; i++) {
            int lin = tid + i * 256;
            int kr = lin / 16;
            int cq = lin % 16;
            float4 bv = *reinterpret_cast<const float4*>(
                &g_H[(size_t)(k0 + kr) * NC + bn * BN + cq * 4]);
            *reinterpret_cast<float4*>(&Bs[kr][cq * 4]) = bv;
        }
        __syncthreads();

        #pragma unroll
        for (int kk = 0; kk < BK; kk++) {
            float a0 = As[kk][ty * 2 + 0];
            float a1 = As[kk][ty * 2 + 1];
            float4 bv = *reinterpret_cast<const float4*>(&Bs[kk][tx * 4]);
            acc[0][0] += a0 * bv.x; acc[0][1] += a0 * bv.y;
            acc[0][2] += a0 * bv.z; acc[0][3] += a0 * bv.w;
            acc[1][0] += a1 * bv.x; acc[1][1] += a1 * bv.y;
            acc[1][2] += a1 * bv.z; acc[1][3] += a1 * bv.w;
        }
        __syncthreads();
    }

    int gm = bm * BM + ty * 2;
    int gc = bn * BN + tx * 4;
    #pragma unroll
    for (int i = 0; i < 2; i++) {
        #pragma unroll
        for (int j = 0; j < 4; j++) {
            int c = gc + j;
            float v = acc[i][j] + __ldg(&b1[c & (Hh - 1)]);
            g_R[(size_t)(gm + i) * NC + c] = fmaxf(v, 0.f);
        }
    }
}

// ---------------------------------------------------------------------------
// K3: out[b,n,l] = sum_h R[n, b*32+h] * W2[h,l] + b2[l]
// block 256 threads (l = tid, active l < 240), 32 rows per block, grid (128, B).
// W2 column held in registers; R rows broadcast from smem.
// ---------------------------------------------------------------------------
__global__ __launch_bounds__(256) void k3_out(const float* __restrict__ W2,
                                              const float* __restrict__ b2,
                                              float* __restrict__ out) {
    __shared__ float Rs[32][Hh];   // 4 KB
    int b  = blockIdx.y;
    int n0 = blockIdx.x * 32;
    int tid = threadIdx.x;

    for (int i = tid; i < 32 * Hh; i += 256) {
        int r = i / Hh, h = i % Hh;
        Rs[r][h] = g_R[(size_t)(n0 + r) * NC + b * Hh + h];
    }
    __syncthreads();

    if (tid < Ll) {
        float w2r[Hh];
        #pragma unroll
        for (int h = 0; h < Hh; h++) w2r[h] = W2[h * Ll + tid];
        float bias = b2[tid];
        #pragma unroll 4
        for (int r = 0; r < 32; r++) {
            float acc = bias;
            #pragma unroll
            for (int h = 0; h < Hh; h++) acc += Rs[r][h] * w2r[h];
            out[((size_t)b * Nn + n0 + r) * Ll + tid] = acc;
        }
    }
}

// ---------------------------------------------------------------------------
extern "C" void kernel_launch(void* const* d_in, const int* in_sizes, int n_in,
                              void* d_out, int out_size) {
    const float* x  = (const float*)d_in[0];
    const float* a  = (const float*)d_in[1];
    const float* W1 = (const float*)d_in[2];
    const float* b1 = (const float*)d_in[3];
    const float* W2 = (const float*)d_in[4];
    const float* b2 = (const float*)d_in[5];
    float* out = (float*)d_out;

    dim3 g1(Nn / 32, Bb), t1(8, 32);
    k1_xw1<<<g1, t1>>>(x, W1);

    dim3 g2(Nn / BM, NC / BN);
    k2_agg<<<g2, 256>>>(a, b1);

    dim3 g3(Nn / 32, Bb);
    k3_out<<<g3, 256>>>(W2, b2, out);
}

// round 4
// speedup vs baseline: 2.9265x; 2.9265x over previous
#include <cuda_runtime.h>
#include <cstdint>

#define Bb 8
#define Nn 4096
#define Ff 240
#define Hh 32
#define Ll 240
#define NC (Bb * Hh)   // 256 folded columns

// Scratch (allocation-free rule: __device__ globals)
__device__ float g_H[Nn * NC];   // H2[m][b*32+h], 4 MB
__device__ float g_R[Nn * NC];   // relu(a@H2 + b1), 4 MB

// ---------------------------------------------------------------------------
// K1: H2[m, b*32+h] = sum_f x[b,m,f] * W1[f,h]   (unchanged from R1)
// ---------------------------------------------------------------------------
__global__ __launch_bounds__(256) void k1_xw1(const float* __restrict__ x,
                                              const float* __restrict__ W1) {
    __shared__ float W1s[Ff][Hh];
    int tid = threadIdx.y * 8 + threadIdx.x;
    for (int i = tid; i < Ff * Hh; i += 256)
        W1s[i / Hh][i % Hh] = W1[i];
    __syncthreads();

    int b   = blockIdx.y;
    int row = blockIdx.x * 32 + threadIdx.y;
    const float* xr = x + ((size_t)b * Nn + row) * Ff;
    int h0 = threadIdx.x * 4;

    float acc0 = 0.f, acc1 = 0.f, acc2 = 0.f, acc3 = 0.f;
    #pragma unroll 4
    for (int f4 = 0; f4 < Ff / 4; f4++) {
        float4 xv = reinterpret_cast<const float4*>(xr)[f4];
        int f = f4 * 4;
        float4 wa = *reinterpret_cast<const float4*>(&W1s[f + 0][h0]);
        float4 wb = *reinterpret_cast<const float4*>(&W1s[f + 1][h0]);
        float4 wc = *reinterpret_cast<const float4*>(&W1s[f + 2][h0]);
        float4 wd = *reinterpret_cast<const float4*>(&W1s[f + 3][h0]);
        acc0 += xv.x * wa.x + xv.y * wb.x + xv.z * wc.x + xv.w * wd.x;
        acc1 += xv.x * wa.y + xv.y * wb.y + xv.z * wc.y + xv.w * wd.y;
        acc2 += xv.x * wa.z + xv.y * wb.z + xv.z * wc.z + xv.w * wd.z;
        acc3 += xv.x * wa.w + xv.y * wb.w + xv.z * wc.w + xv.w * wd.w;
    }
    float* dst = &g_H[(size_t)row * NC + b * Hh + h0];
    dst[0] = acc0; dst[1] = acc1; dst[2] = acc2; dst[3] = acc3;
}

// ---------------------------------------------------------------------------
// K2 (tensor cores): R = relu(a @ g_H + b1)
// GEMM M=4096, N=256, K=4096 via mma.sync.m16n8k8.tf32.
// BM=128, BN=64, BK=32. 256 thr = 8 warps (4x2), warp tile 32x32.
// cp.async double-buffered smem; conflict-free fragment loads.
// ---------------------------------------------------------------------------
#define K2_BM 128
#define K2_BN 64
#define K2_BK 32
#define ASTR 36          // A smem row stride (floats): bank = 4*r + c, conflict-free
#define BSTR 72          // B smem row stride (floats): bank = 8*k + n, conflict-free
#define K2_NIT (Nn / K2_BK)
#define ABUF (K2_BM * ASTR)      // 4608 floats per buffer
#define BBUF (K2_BK * BSTR)      // 2304 floats per buffer
#define K2_SMEM ((2 * ABUF + 2 * BBUF) * 4)   // 55296 bytes

__device__ __forceinline__ void cpasync16(void* dst, const void* src) {
    uint32_t d = (uint32_t)__cvta_generic_to_shared(dst);
    asm volatile("cp.async.ca.shared.global [%0], [%1], 16;\n" :: "r"(d), "l"(src));
}
__device__ __forceinline__ uint32_t f2tf32(float f) {
    uint32_t r;
    asm("cvt.rna.tf32.f32 %0, %1;" : "=r"(r) : "f"(f));
    return r;
}
__device__ __forceinline__ void mma_tf32(float c[4], const uint32_t a[4],
                                         const uint32_t b[2]) {
    asm volatile(
        "mma.sync.aligned.m16n8k8.row.col.f32.tf32.tf32.f32 "
        "{%0,%1,%2,%3}, {%4,%5,%6,%7}, {%8,%9}, {%0,%1,%2,%3};"
        : "+f"(c[0]), "+f"(c[1]), "+f"(c[2]), "+f"(c[3])
        : "r"(a[0]), "r"(a[1]), "r"(a[2]), "r"(a[3]), "r"(b[0]), "r"(b[1]));
}

__global__ __launch_bounds__(256) void k2_tc(const float* __restrict__ A,
                                             const float* __restrict__ b1) {
    extern __shared__ float sm[];
    float* As = sm;                  // [2][128][ASTR]
    float* Bs = sm + 2 * ABUF;       // [2][32][BSTR]

    const int tid  = threadIdx.x;
    const int warp = tid >> 5;
    const int lane = tid & 31;
    const int bm = blockIdx.x * K2_BM;
    const int bn = blockIdx.y * K2_BN;

    const int wm = (warp & 3) * 32;      // warp M offset within tile
    const int wn = (warp >> 2) * 32;     // warp N offset within tile

    // cp.async mappings
    const int a_row = tid >> 3;          // 0..31 base, + i*32
    const int a_k4  = (tid & 7) * 4;     // float4 offset in k
    const int b_kr  = tid >> 4;          // 0..15 base, + i*16
    const int b_n4  = (tid & 15) * 4;

    // tile loaders
    auto load_tiles = [&](int buf, int k0) {
        float* ab = As + buf * ABUF;
        float* bb = Bs + buf * BBUF;
        #pragma unroll
        for (int i = 0; i < 4; i++) {
            int row = a_row + i * 32;
            cpasync16(ab + row * ASTR + a_k4,
                      A + (size_t)(bm + row) * Nn + k0 + a_k4);
        }
        #pragma unroll
        for (int i = 0; i < 2; i++) {
            int kr = b_kr + i * 16;
            cpasync16(bb + kr * BSTR + b_n4,
                      g_H + (size_t)(k0 + kr) * NC + bn + b_n4);
        }
    };

    float acc[2][4][4];
    #pragma unroll
    for (int mi = 0; mi < 2; mi++)
        #pragma unroll
        for (int ni = 0; ni < 4; ni++)
            #pragma unroll
            for (int q = 0; q < 4; q++) acc[mi][ni][q] = 0.f;

    const int r  = lane >> 2;   // 0..7
    const int cc = lane & 3;    // 0..3

    // prologue
    load_tiles(0, 0);
    asm volatile("cp.async.commit_group;\n");

    for (int iter = 0; iter < K2_NIT; iter++) {
        int cbuf = iter & 1;
        if (iter + 1 < K2_NIT) load_tiles((iter + 1) & 1, (iter + 1) * K2_BK);
        asm volatile("cp.async.commit_group;\n");
        asm volatile("cp.async.wait_group 1;\n");
        __syncthreads();

        const float* as = As + cbuf * ABUF;
        const float* bs = Bs + cbuf * BBUF;

        #pragma unroll
        for (int kk = 0; kk < K2_BK; kk += 8) {
            uint32_t af[2][4];
            #pragma unroll
            for (int mi = 0; mi < 2; mi++) {
                const float* ap = as + (wm + mi * 16 + r) * ASTR + kk + cc;
                af[mi][0] = f2tf32(ap[0]);
                af[mi][1] = f2tf32(ap[8 * ASTR]);
                af[mi][2] = f2tf32(ap[4]);
                af[mi][3] = f2tf32(ap[8 * ASTR + 4]);
            }
            uint32_t bf[4][2];
            #pragma unroll
            for (int ni = 0; ni < 4; ni++) {
                const float* bp = bs + (kk + cc) * BSTR + wn + ni * 8 + r;
                bf[ni][0] = f2tf32(bp[0]);
                bf[ni][1] = f2tf32(bp[4 * BSTR]);
            }
            #pragma unroll
            for (int mi = 0; mi < 2; mi++)
                #pragma unroll
                for (int ni = 0; ni < 4; ni++)
                    mma_tf32(acc[mi][ni], af[mi], bf[ni]);
        }
        __syncthreads();
    }

    // epilogue: bias (broadcast per 32-col group) + relu, float2 stores
    #pragma unroll
    for (int mi = 0; mi < 2; mi++) {
        #pragma unroll
        for (int ni = 0; ni < 4; ni++) {
            int gm = bm + wm + mi * 16 + r;
            int gc = bn + wn + ni * 8 + cc * 2;
            float bv0 = __ldg(&b1[gc & (Hh - 1)]);
            float bv1 = __ldg(&b1[(gc + 1) & (Hh - 1)]);
            float2 v0, v1;
            v0.x = fmaxf(acc[mi][ni][0] + bv0, 0.f);
            v0.y = fmaxf(acc[mi][ni][1] + bv1, 0.f);
            v1.x = fmaxf(acc[mi][ni][2] + bv0, 0.f);
            v1.y = fmaxf(acc[mi][ni][3] + bv1, 0.f);
            *reinterpret_cast<float2*>(&g_R[(size_t)gm * NC + gc])       = v0;
            *reinterpret_cast<float2*>(&g_R[(size_t)(gm + 8) * NC + gc]) = v1;
        }
    }
}

// ---------------------------------------------------------------------------
// K3: out[b,n,l] = sum_h R[n, b*32+h] * W2[h,l] + b2[l]   (unchanged)
// ---------------------------------------------------------------------------
__global__ __launch_bounds__(256) void k3_out(const float* __restrict__ W2,
                                              const float* __restrict__ b2,
                                              float* __restrict__ out) {
    __shared__ float Rs[32][Hh];
    int b  = blockIdx.y;
    int n0 = blockIdx.x * 32;
    int tid = threadIdx.x;

    for (int i = tid; i < 32 * Hh; i += 256) {
        int rr = i / Hh, h = i % Hh;
        Rs[rr][h] = g_R[(size_t)(n0 + rr) * NC + b * Hh + h];
    }
    __syncthreads();

    if (tid < Ll) {
        float w2r[Hh];
        #pragma unroll
        for (int h = 0; h < Hh; h++) w2r[h] = W2[h * Ll + tid];
        float bias = b2[tid];
        #pragma unroll 4
        for (int rr = 0; rr < 32; rr++) {
            float acc = bias;
            #pragma unroll
            for (int h = 0; h < Hh; h++) acc += Rs[rr][h] * w2r[h];
            out[((size_t)b * Nn + n0 + rr) * Ll + tid] = acc;
        }
    }
}

// ---------------------------------------------------------------------------
extern "C" void kernel_launch(void* const* d_in, const int* in_sizes, int n_in,
                              void* d_out, int out_size) {
    const float* x  = (const float*)d_in[0];
    const float* a  = (const float*)d_in[1];
    const float* W1 = (const float*)d_in[2];
    const float* b1 = (const float*)d_in[3];
    const float* W2 = (const float*)d_in[4];
    const float* b2 = (const float*)d_in[5];
    float* out = (float*)d_out;

    dim3 g1(Nn / 32, Bb), t1(8, 32);
    k1_xw1<<<g1, t1>>>(x, W1);

    cudaFuncSetAttribute(k2_tc, cudaFuncAttributeMaxDynamicSharedMemorySize,
                         K2_SMEM);
    dim3 g2(Nn / K2_BM, NC / K2_BN);
    k2_tc<<<g2, 256, K2_SMEM>>>(a, b1);

    dim3 g3(Nn / 32, Bb);
    k3_out<<<g3, 256>>>(W2, b2, out);
}

// round 5
// speedup vs baseline: 3.4310x; 1.1724x over previous
#include <cuda_runtime.h>
#include <cstdint>

#define Bb 8
#define Nn 4096
#define Ff 240
#define Hh 32
#define Ll 240
#define NC (Bb * Hh)   // 256 folded columns

// Scratch (allocation-free rule: __device__ globals)
__device__ float g_H[Nn * NC];        // H2[m][b*32+h], 4 MB
__device__ float g_P[2 * Nn * NC];    // split-K partials, 8 MB

// ---------------------------------------------------------------------------
// K1 v2: H2[m, b*32+h] = sum_f x[b,m,f] * W1[f,h]
// 4 rows x 4 h per thread -> W1 smem LDS amortized 4x (FFMA-bound).
// block (8,32), grid (N/128, B).
// ---------------------------------------------------------------------------
__global__ __launch_bounds__(256) void k1_xw1(const float* __restrict__ x,
                                              const float* __restrict__ W1) {
    __shared__ float W1s[Ff][Hh];
    int tid = threadIdx.y * 8 + threadIdx.x;
    for (int i = tid; i < Ff * Hh; i += 256)
        W1s[i / Hh][i % Hh] = W1[i];
    __syncthreads();

    int b    = blockIdx.y;
    int row0 = blockIdx.x * 128 + threadIdx.y * 4;
    int h0   = threadIdx.x * 4;
    const float* xr = x + ((size_t)b * Nn + row0) * Ff;

    float acc[4][4];
    #pragma unroll
    for (int r = 0; r < 4; r++)
        #pragma unroll
        for (int h = 0; h < 4; h++) acc[r][h] = 0.f;

    #pragma unroll 4
    for (int f4 = 0; f4 < Ff / 4; f4++) {
        int f = f4 * 4;
        float4 wa = *reinterpret_cast<const float4*>(&W1s[f + 0][h0]);
        float4 wb = *reinterpret_cast<const float4*>(&W1s[f + 1][h0]);
        float4 wc = *reinterpret_cast<const float4*>(&W1s[f + 2][h0]);
        float4 wd = *reinterpret_cast<const float4*>(&W1s[f + 3][h0]);
        #pragma unroll
        for (int r = 0; r < 4; r++) {
            float4 xv = *reinterpret_cast<const float4*>(xr + (size_t)r * Ff + f);
            acc[r][0] += xv.x * wa.x + xv.y * wb.x + xv.z * wc.x + xv.w * wd.x;
            acc[r][1] += xv.x * wa.y + xv.y * wb.y + xv.z * wc.y + xv.w * wd.y;
            acc[r][2] += xv.x * wa.z + xv.y * wb.z + xv.z * wc.z + xv.w * wd.z;
            acc[r][3] += xv.x * wa.w + xv.y * wb.w + xv.z * wc.w + xv.w * wd.w;
        }
    }
    #pragma unroll
    for (int r = 0; r < 4; r++) {
        float4 v = make_float4(acc[r][0], acc[r][1], acc[r][2], acc[r][3]);
        *reinterpret_cast<float4*>(&g_H[(size_t)(row0 + r) * NC + b * Hh + h0]) = v;
    }
}

// ---------------------------------------------------------------------------
// K2 v2: split-K tf32 tensor-core GEMM, partials only (bias/relu in k3).
// M=4096, N=256, K=2048 per z-half. BM=128, BN=64, BK=32, 256 thr, 8 warps.
// 3-stage cp.async ring, ONE __syncthreads per iter.
// ---------------------------------------------------------------------------
#define K2_BM 128
#define K2_BN 64
#define K2_BK 32
#define KSPLIT 2
#define KHALF (Nn / KSPLIT)
#define K2_NIT (KHALF / K2_BK)       // 64
#define ASTR 36
#define BSTR 72
#define ABUF (K2_BM * ASTR)          // 4608 floats
#define BBUF (K2_BK * BSTR)          // 2304 floats
#define STAGES 3
#define K2_SMEM (STAGES * (ABUF + BBUF) * 4)   // 82944 bytes

__device__ __forceinline__ void cpasync16(void* dst, const void* src) {
    uint32_t d = (uint32_t)__cvta_generic_to_shared(dst);
    asm volatile("cp.async.ca.shared.global [%0], [%1], 16;\n" :: "r"(d), "l"(src));
}
__device__ __forceinline__ uint32_t f2tf32(float f) {
    uint32_t r;
    asm("cvt.rna.tf32.f32 %0, %1;" : "=r"(r) : "f"(f));
    return r;
}
__device__ __forceinline__ void mma_tf32(float c[4], const uint32_t a[4],
                                         const uint32_t b[2]) {
    asm volatile(
        "mma.sync.aligned.m16n8k8.row.col.f32.tf32.tf32.f32 "
        "{%0,%1,%2,%3}, {%4,%5,%6,%7}, {%8,%9}, {%0,%1,%2,%3};"
        : "+f"(c[0]), "+f"(c[1]), "+f"(c[2]), "+f"(c[3])
        : "r"(a[0]), "r"(a[1]), "r"(a[2]), "r"(a[3]), "r"(b[0]), "r"(b[1]));
}

__global__ __launch_bounds__(256) void k2_tc(const float* __restrict__ A) {
    extern __shared__ float sm[];

    const int tid  = threadIdx.x;
    const int warp = tid >> 5;
    const int lane = tid & 31;
    const int bm = blockIdx.x * K2_BM;
    const int bn = blockIdx.y * K2_BN;
    const int kz = blockIdx.z;
    const int kbase = kz * KHALF;

    const int wm = (warp & 3) * 32;
    const int wn = (warp >> 2) * 32;

    const int a_row = tid >> 3;
    const int a_k4  = (tid & 7) * 4;
    const int b_kr  = tid >> 4;
    const int b_n4  = (tid & 15) * 4;

    auto load_tiles = [&](int stg, int k0) {
        float* ab = sm + stg * (ABUF + BBUF);
        float* bb = ab + ABUF;
        #pragma unroll
        for (int i = 0; i < 4; i++) {
            int row = a_row + i * 32;
            cpasync16(ab + row * ASTR + a_k4,
                      A + (size_t)(bm + row) * Nn + kbase + k0 + a_k4);
        }
        #pragma unroll
        for (int i = 0; i < 2; i++) {
            int kr = b_kr + i * 16;
            cpasync16(bb + kr * BSTR + b_n4,
                      g_H + (size_t)(kbase + k0 + kr) * NC + bn + b_n4);
        }
    };

    float acc[2][4][4];
    #pragma unroll
    for (int mi = 0; mi < 2; mi++)
        #pragma unroll
        for (int ni = 0; ni < 4; ni++)
            #pragma unroll
            for (int q = 0; q < 4; q++) acc[mi][ni][q] = 0.f;

    const int r  = lane >> 2;
    const int cc = lane & 3;

    // prologue: stages 0,1
    load_tiles(0, 0);
    asm volatile("cp.async.commit_group;\n");
    load_tiles(1, K2_BK);
    asm volatile("cp.async.commit_group;\n");

    int stg = 0;
    for (int iter = 0; iter < K2_NIT; iter++) {
        asm volatile("cp.async.wait_group 1;\n");
        __syncthreads();

        // issue load for iter+2 into the buffer freed by compute(iter-1)
        if (iter + 2 < K2_NIT) {
            int nstg = stg + 2; if (nstg >= STAGES) nstg -= STAGES;
            load_tiles(nstg, (iter + 2) * K2_BK);
        }
        asm volatile("cp.async.commit_group;\n");

        const float* as = sm + stg * (ABUF + BBUF);
        const float* bs = as + ABUF;

        #pragma unroll
        for (int kk = 0; kk < K2_BK; kk += 8) {
            uint32_t af[2][4];
            #pragma unroll
            for (int mi = 0; mi < 2; mi++) {
                const float* ap = as + (wm + mi * 16 + r) * ASTR + kk + cc;
                af[mi][0] = f2tf32(ap[0]);
                af[mi][1] = f2tf32(ap[8 * ASTR]);
                af[mi][2] = f2tf32(ap[4]);
                af[mi][3] = f2tf32(ap[8 * ASTR + 4]);
            }
            uint32_t bf[4][2];
            #pragma unroll
            for (int ni = 0; ni < 4; ni++) {
                const float* bp = bs + (kk + cc) * BSTR + wn + ni * 8 + r;
                bf[ni][0] = f2tf32(bp[0]);
                bf[ni][1] = f2tf32(bp[4 * BSTR]);
            }
            #pragma unroll
            for (int mi = 0; mi < 2; mi++)
                #pragma unroll
                for (int ni = 0; ni < 4; ni++)
                    mma_tf32(acc[mi][ni], af[mi], bf[ni]);
        }

        stg++; if (stg >= STAGES) stg = 0;
    }

    // epilogue: store raw partials
    float* P = g_P + (size_t)kz * Nn * NC;
    #pragma unroll
    for (int mi = 0; mi < 2; mi++) {
        #pragma unroll
        for (int ni = 0; ni < 4; ni++) {
            int gm = bm + wm + mi * 16 + r;
            int gc = bn + wn + ni * 8 + cc * 2;
            float2 v0 = make_float2(acc[mi][ni][0], acc[mi][ni][1]);
            float2 v1 = make_float2(acc[mi][ni][2], acc[mi][ni][3]);
            *reinterpret_cast<float2*>(&P[(size_t)gm * NC + gc])       = v0;
            *reinterpret_cast<float2*>(&P[(size_t)(gm + 8) * NC + gc]) = v1;
        }
    }
}

// ---------------------------------------------------------------------------
// K3 v2: out[b,n,l] = sum_h relu(P0+P1+b1)[n, b*32+h] * W2[h,l] + b2[l]
// Fuses the split-K reduction + bias + relu.
// ---------------------------------------------------------------------------
__global__ __launch_bounds__(256) void k3_out(const float* __restrict__ b1,
                                              const float* __restrict__ W2,
                                              const float* __restrict__ b2,
                                              float* __restrict__ out) {
    __shared__ float Rs[32][Hh];
    int b  = blockIdx.y;
    int n0 = blockIdx.x * 32;
    int tid = threadIdx.x;

    const float* P0 = g_P;
    const float* P1 = g_P + (size_t)Nn * NC;
    for (int i = tid; i < 32 * Hh; i += 256) {
        int rr = i / Hh, h = i % Hh;
        size_t idx = (size_t)(n0 + rr) * NC + b * Hh + h;
        Rs[rr][h] = fmaxf(P0[idx] + P1[idx] + b1[h], 0.f);
    }
    __syncthreads();

    if (tid < Ll) {
        float w2r[Hh];
        #pragma unroll
        for (int h = 0; h < Hh; h++) w2r[h] = W2[h * Ll + tid];
        float bias = b2[tid];
        #pragma unroll 4
        for (int rr = 0; rr < 32; rr++) {
            float acc = bias;
            #pragma unroll
            for (int h = 0; h < Hh; h++) acc += Rs[rr][h] * w2r[h];
            out[((size_t)b * Nn + n0 + rr) * Ll + tid] = acc;
        }
    }
}

// ---------------------------------------------------------------------------
extern "C" void kernel_launch(void* const* d_in, const int* in_sizes, int n_in,
                              void* d_out, int out_size) {
    const float* x  = (const float*)d_in[0];
    const float* a  = (const float*)d_in[1];
    const float* W1 = (const float*)d_in[2];
    const float* b1 = (const float*)d_in[3];
    const float* W2 = (const float*)d_in[4];
    const float* b2 = (const float*)d_in[5];
    float* out = (float*)d_out;

    dim3 g1(Nn / 128, Bb), t1(8, 32);
    k1_xw1<<<g1, t1>>>(x, W1);

    cudaFuncSetAttribute(k2_tc, cudaFuncAttributeMaxDynamicSharedMemorySize,
                         K2_SMEM);
    dim3 g2(Nn / K2_BM, NC / K2_BN, KSPLIT);
    k2_tc<<<g2, 256, K2_SMEM>>>(a);

    dim3 g3(Nn / 32, Bb);
    k3_out<<<g3, 256>>>(b1, W2, b2, out);
}

// round 8
// speedup vs baseline: 3.9886x; 1.1625x over previous
#include <cuda_runtime.h>
#include <cstdint>

#define Bb 8
#define Nn 4096
#define Ff 240
#define Hh 32
#define Ll 240
#define NC (Bb * Hh)   // 256 folded columns
#define KSPLIT 4
#define KCHUNK (Nn / KSPLIT)      // 1024

// Scratch (allocation-free rule: __device__ globals)
__device__ float g_Ht[NC * Nn];          // H transposed [c][k], tf32-rounded, 4 MB
__device__ float g_P[KSPLIT * Nn * NC];  // split-K partials, c-major [kz][c][m], 16 MB

// ===========================================================================
__device__ __forceinline__ void cpasync16(void* dst, const void* src) {
    uint32_t d = (uint32_t)__cvta_generic_to_shared(dst);
    asm volatile("cp.async.cg.shared.global [%0], [%1], 16;\n" :: "r"(d), "l"(src));
}
__device__ __forceinline__ uint32_t f2tf32(float f) {
    uint32_t r;
    asm("cvt.rna.tf32.f32 %0, %1;" : "=r"(r) : "f"(f));
    return r;
}
__device__ __forceinline__ void mma_tf32(float c[4], const uint32_t a[4],
                                         const uint32_t b[2]) {
    asm volatile(
        "mma.sync.aligned.m16n8k8.row.col.f32.tf32.tf32.f32 "
        "{%0,%1,%2,%3}, {%4,%5,%6,%7}, {%8,%9}, {%0,%1,%2,%3};"
        : "+f"(c[0]), "+f"(c[1]), "+f"(c[2]), "+f"(c[3])
        : "r"(a[0]), "r"(a[1]), "r"(a[2]), "r"(a[3]), "r"(b[0]), "r"(b[1]));
}

// ===========================================================================
// K1: g_Ht[b*32+h][m] = tf32_rna( sum_f x[b,m,f] * W1[f,h] )
// 2 rows x 4 h per thread; grid (N/64, B) = 512 CTAs.
// ===========================================================================
__global__ __launch_bounds__(256) void k1_xw1(const float* __restrict__ x,
                                              const float* __restrict__ W1) {
    __shared__ float W1s[Ff][Hh];
    int tid = threadIdx.y * 8 + threadIdx.x;
    for (int i = tid; i < Ff * Hh; i += 256)
        W1s[i / Hh][i % Hh] = W1[i];
    __syncthreads();

    int b    = blockIdx.y;
    int row0 = blockIdx.x * 64 + threadIdx.y * 2;
    int h0   = threadIdx.x * 4;
    const float* xr = x + ((size_t)b * Nn + row0) * Ff;

    float acc[2][4];
    #pragma unroll
    for (int r = 0; r < 2; r++)
        #pragma unroll
        for (int h = 0; h < 4; h++) acc[r][h] = 0.f;

    #pragma unroll 4
    for (int f4 = 0; f4 < Ff / 4; f4++) {
        int f = f4 * 4;
        float4 wa = *reinterpret_cast<const float4*>(&W1s[f + 0][h0]);
        float4 wb = *reinterpret_cast<const float4*>(&W1s[f + 1][h0]);
        float4 wc = *reinterpret_cast<const float4*>(&W1s[f + 2][h0]);
        float4 wd = *reinterpret_cast<const float4*>(&W1s[f + 3][h0]);
        #pragma unroll
        for (int r = 0; r < 2; r++) {
            float4 xv = *reinterpret_cast<const float4*>(xr + (size_t)r * Ff + f);
            acc[r][0] += xv.x * wa.x + xv.y * wb.x + xv.z * wc.x + xv.w * wd.x;
            acc[r][1] += xv.x * wa.y + xv.y * wb.y + xv.z * wc.y + xv.w * wd.y;
            acc[r][2] += xv.x * wa.z + xv.y * wb.z + xv.z * wc.z + xv.w * wd.z;
            acc[r][3] += xv.x * wa.w + xv.y * wb.w + xv.z * wc.w + xv.w * wd.w;
        }
    }
    #pragma unroll
    for (int j = 0; j < 4; j++) {
        float2 v;
        v.x = __uint_as_float(f2tf32(acc[0][j]));
        v.y = __uint_as_float(f2tf32(acc[1][j]));
        *reinterpret_cast<float2*>(
            &g_Ht[(size_t)(b * Hh + h0 + j) * Nn + row0]) = v;
    }
}

// ===========================================================================
// K2: split-K tf32 mma.sync GEMM, BN = full 256 (A read exactly once).
// Per CTA: P[kz][0:256][bm:bm+128] += A[bm:, kz-chunk] @ Ht[:, kz-chunk]^T
// BM=128, BN=256, BK=32; 512 thr = 16 warps (4m x 4n), warp tile 32x64.
// 3-stage cp.async ring, 1 syncthreads/iter, no CVT in mainloop.
// ===========================================================================
#define K2_BM 128
#define K2_BN 256
#define K2_BK 32
#define K2_NIT (KCHUNK / K2_BK)    // 32
#define ASTR 36
#define BSTR 36
#define ABUF (K2_BM * ASTR)        // 4608 floats
#define BBUF (K2_BN * BSTR)        // 9216 floats
#define STAGEF (ABUF + BBUF)       // 13824 floats = 55296 B
#define STAGES 3
#define K2_SMEM (STAGES * STAGEF * 4)   // 165888 B

__global__ __launch_bounds__(512) void k2_tc(const float* __restrict__ A) {
    extern __shared__ float sm[];

    const int tid  = threadIdx.x;
    const int warp = tid >> 5;
    const int lane = tid & 31;
    const int bm   = blockIdx.x * K2_BM;
    const int kz   = blockIdx.y;
    const int kbase = kz * KCHUNK;

    const int wm = (warp & 3) * 32;       // warp M offset
    const int wn = (warp >> 2) * 64;      // warp N offset

    // cp.async mappings (512 threads)
    const int a_row = tid >> 3;           // 0..63 (+64)
    const int a_k4  = (tid & 7) * 4;
    const int b_c   = tid >> 3;           // 0..63 (+64,128,192)
    const int b_k4  = (tid & 7) * 4;

    auto load_tile = [&](int stg, int it) {
        float* ab = sm + stg * STAGEF;
        float* bb = ab + ABUF;
        int kcol = kbase + it * K2_BK;
        #pragma unroll
        for (int t = 0; t < 2; t++) {
            int row = a_row + t * 64;
            cpasync16(ab + row * ASTR + a_k4,
                      A + (size_t)(bm + row) * Nn + kcol + a_k4);
        }
        #pragma unroll
        for (int t = 0; t < 4; t++) {
            int c = b_c + t * 64;
            cpasync16(bb + c * BSTR + b_k4,
                      g_Ht + (size_t)c * Nn + kcol + b_k4);
        }
    };

    float acc[2][8][4];
    #pragma unroll
    for (int mi = 0; mi < 2; mi++)
        #pragma unroll
        for (int ni = 0; ni < 8; ni++)
            #pragma unroll
            for (int q = 0; q < 4; q++) acc[mi][ni][q] = 0.f;

    const int r  = lane >> 2;
    const int cc = lane & 3;

    // prologue
    load_tile(0, 0);
    asm volatile("cp.async.commit_group;\n");
    load_tile(1, 1);
    asm volatile("cp.async.commit_group;\n");

    for (int i = 0; i < K2_NIT; i++) {
        asm volatile("cp.async.wait_group 1;\n");
        __syncthreads();
        if (i + 2 < K2_NIT) load_tile((i + 2) % STAGES, i + 2);
        asm volatile("cp.async.commit_group;\n");

        const float* as = sm + (i % STAGES) * STAGEF;
        const float* bs = as + ABUF;

        #pragma unroll
        for (int kk = 0; kk < K2_BK; kk += 8) {
            uint32_t af[2][4];
            #pragma unroll
            for (int mi = 0; mi < 2; mi++) {
                const float* ap = as + (wm + mi * 16 + r) * ASTR + kk + cc;
                af[mi][0] = __float_as_uint(ap[0]);            // HW tf32 truncation
                af[mi][1] = __float_as_uint(ap[8 * ASTR]);
                af[mi][2] = __float_as_uint(ap[4]);
                af[mi][3] = __float_as_uint(ap[8 * ASTR + 4]);
            }
            uint32_t bf[8][2];
            #pragma unroll
            for (int ni = 0; ni < 8; ni++) {
                const float* bp = bs + (wn + ni * 8 + r) * BSTR + kk + cc;
                bf[ni][0] = __float_as_uint(bp[0]);            // pre-rounded in k1
                bf[ni][1] = __float_as_uint(bp[4]);
            }
            #pragma unroll
            for (int mi = 0; mi < 2; mi++)
                #pragma unroll
                for (int ni = 0; ni < 8; ni++)
                    mma_tf32(acc[mi][ni], af[mi], bf[ni]);
        }
    }

    // epilogue: raw partials, c-major [c][m]
    float* P = g_P + (size_t)kz * Nn * NC;
    #pragma unroll
    for (int mi = 0; mi < 2; mi++) {
        #pragma unroll
        for (int ni = 0; ni < 8; ni++) {
            int gm = bm + wm + mi * 16 + r;
            int gc = wn + ni * 8 + cc * 2;
            P[(size_t)gc * Nn + gm]           = acc[mi][ni][0];
            P[(size_t)(gc + 1) * Nn + gm]     = acc[mi][ni][1];
            P[(size_t)gc * Nn + gm + 8]       = acc[mi][ni][2];
            P[(size_t)(gc + 1) * Nn + gm + 8] = acc[mi][ni][3];
        }
    }
}

// ===========================================================================
// K3: out[b,n,l] = sum_h relu(sum_z Pz[b*32+h][n] + b1[h]) * W2[h,l] + b2[l]
// ===========================================================================
__global__ __launch_bounds__(256) void k3_out(const float* __restrict__ b1,
                                              const float* __restrict__ W2,
                                              const float* __restrict__ b2,
                                              float* __restrict__ out) {
    __shared__ float Rs[32][Hh];
    int b  = blockIdx.y;
    int n0 = blockIdx.x * 32;
    int tid = threadIdx.x;

    for (int i = tid; i < 32 * Hh; i += 256) {
        int h = i >> 5, rr = i & 31;   // coalesced along n
        size_t idx = (size_t)(b * Hh + h) * Nn + n0 + rr;
        float s = g_P[idx]
                + g_P[idx + (size_t)1 * Nn * NC]
                + g_P[idx + (size_t)2 * Nn * NC]
                + g_P[idx + (size_t)3 * Nn * NC];
        Rs[rr][h] = fmaxf(s + b1[h], 0.f);
    }
    __syncthreads();

    if (tid < Ll) {
        float w2r[Hh];
        #pragma unroll
        for (int h = 0; h < Hh; h++) w2r[h] = W2[h * Ll + tid];
        float bias = b2[tid];
        #pragma unroll 4
        for (int rr = 0; rr < 32; rr++) {
            float acc = bias;
            #pragma unroll
            for (int h = 0; h < Hh; h++) acc += Rs[rr][h] * w2r[h];
            out[((size_t)b * Nn + n0 + rr) * Ll + tid] = acc;
        }
    }
}

// ===========================================================================
extern "C" void kernel_launch(void* const* d_in, const int* in_sizes, int n_in,
                              void* d_out, int out_size) {
    const float* x  = (const float*)d_in[0];
    const float* a  = (const float*)d_in[1];
    const float* W1 = (const float*)d_in[2];
    const float* b1 = (const float*)d_in[3];
    const float* W2 = (const float*)d_in[4];
    const float* b2 = (const float*)d_in[5];
    float* out = (float*)d_out;

    dim3 g1(Nn / 64, Bb), t1(8, 32);
    k1_xw1<<<g1, t1>>>(x, W1);

    cudaFuncSetAttribute(k2_tc, cudaFuncAttributeMaxDynamicSharedMemorySize,
                         K2_SMEM);
    dim3 g2(Nn / K2_BM, KSPLIT);
    k2_tc<<<g2, 512, K2_SMEM>>>(a);

    dim3 g3(Nn / 32, Bb);
    k3_out<<<g3, 256>>>(b1, W2, b2, out);
}